// round 5
// baseline (speedup 1.0000x reference)
#include <cuda_runtime.h>
#include <math.h>

// Problem dims
#define BB    32
#define TENC  1024
#define ENCD  1024
#define DECD  1024
#define MELD  80
// Attention split
#define NC    64          // chunks over T
#define CT    16          // timesteps per chunk (64 KB smem tile)
// LSTM GEMM
#define KTOT  2128        // 80 (mel) + 1024 (ctx) + 1024 (h)
#define TK    16
#define NTILES 133        // 2128/16
#define KSPLIT 19
#define TPS    7          // 133/19

// Output layout: [mel(32*80), h_new(32*1024), c_new(32*1024)]
#define OFF_MEL 0
#define OFF_H   (BB*MELD)
#define OFF_C   (BB*MELD + BB*DECD)

// Scratch (static device memory — no allocations allowed)
__device__ float g_m[BB*NC];
__device__ float g_l[BB*NC];
__device__ float g_acc[BB*NC*ENCD];        // 8 MB
__device__ float g_ctx[BB*ENCD];
__device__ float g_zp[KSPLIT*BB*4*DECD];

#define LOG2E  1.4426950408889634f
#define LOG2E2 2.8853900817779268f

// HW tanh (MUFU.TANH) — attention scores only; error damped by softmax+GEMM.
__device__ __forceinline__ float tanhA(float x) {
    float y; asm("tanh.approx.f32 %0, %1;" : "=f"(y) : "f"(x)); return y;
}
// Accurate-ish versions for the LSTM gate outputs (written directly to d_out)
__device__ __forceinline__ float fast_tanh(float x) {
    float u = exp2f(x * LOG2E2);
    return 1.0f - __fdividef(2.0f, u + 1.0f);
}
__device__ __forceinline__ float fast_sig(float x) {
    return __fdividef(1.0f, 1.0f + exp2f(-LOG2E * x));
}

// f32x2 packed FMA helpers
typedef unsigned long long u64t;
__device__ __forceinline__ u64t pack2(float w) {
    u64t r; asm("mov.b64 %0, {%1, %1};" : "=l"(r) : "f"(w)); return r;
}
__device__ __forceinline__ void fma2(u64t& a, u64t x, u64t w) {
    asm("fma.rn.f32x2 %0, %1, %2, %0;" : "+l"(a) : "l"(x), "l"(w));
}
__device__ __forceinline__ float2 unpack2(u64t a) {
    float2 f; asm("mov.b64 {%0, %1}, %2;" : "=f"(f.x), "=f"(f.y) : "l"(a)); return f;
}

// ---------------------------------------------------------------------------
// Kernel A: attention chunk partials. Grid (B, NC), 256 threads (8 warps),
// 64 KB dynamic smem tile (CT x 1024 floats).
// Phase A: warp w streams rows t=2w,2w+1 DRAM->regs, computes scores, and
//          parks the rows in smem.
// Merge:   warp 0 does chunk-local softmax over the 16 scores.
// Phase B: warp w owns D-slice [128w,128w+128), accumulates float4/lane
//          from SMEM (no L2 re-read).
// enc touches DRAM exactly once; phase B is LDS-fed.
// ---------------------------------------------------------------------------
__global__ void __launch_bounds__(256) attn_partial(
    const float* __restrict__ enc, const float* __restrict__ h,
    const float* __restrict__ scale)
{
    extern __shared__ float es[];          // CT*ENCD floats = 64 KB
    const int b = blockIdx.x, c = blockIdx.y;
    const int tid = threadIdx.x;
    const int wid = tid >> 5, lane = tid & 31;

    // Per-lane D-slice for phase A: float4 granule d4 = lane + 32k, k=0..7
    float4 hs[8], sc[8];
    const float4* h4 = (const float4*)(h + b*DECD);
    const float4* s4 = (const float4*)scale;
    #pragma unroll
    for (int k = 0; k < 8; k++) { hs[k] = h4[lane + 32*k]; sc[k] = s4[lane + 32*k]; }

    __shared__ float s_sm[CT];
    __shared__ float w_sm[CT];

    const float* encb = enc + ((long)(b*TENC) + c*CT)*ENCD;

    // ---- Phase A: load + score + park in smem ----
    #pragma unroll
    for (int i = 0; i < 2; i++) {
        const int t = wid*2 + i;
        const float4* eA = (const float4*)(encb + t*ENCD) + lane;
        float4*       eS = (float4*)(es + t*ENCD) + lane;
        float p0 = 0.f, p1 = 0.f, p2 = 0.f, p3 = 0.f;
        #pragma unroll
        for (int k = 0; k < 8; k++) {
            float4 e = eA[32*k];
            eS[32*k] = e;
            p0 = fmaf(sc[k].x, tanhA(hs[k].x + e.x), p0);
            p1 = fmaf(sc[k].y, tanhA(hs[k].y + e.y), p1);
            p2 = fmaf(sc[k].z, tanhA(hs[k].z + e.z), p2);
            p3 = fmaf(sc[k].w, tanhA(hs[k].w + e.w), p3);
        }
        float s = (p0 + p1) + (p2 + p3);
        #pragma unroll
        for (int off = 16; off > 0; off >>= 1)
            s += __shfl_xor_sync(0xffffffffu, s, off);
        if (lane == 0) s_sm[t] = s;
    }
    __syncthreads();

    // ---- Merge: chunk-local softmax (warp 0; lanes mirror over 16) ----
    if (wid == 0) {
        float s = s_sm[lane & 15];
        float m = s;
        #pragma unroll
        for (int off = 8; off > 0; off >>= 1)
            m = fmaxf(m, __shfl_xor_sync(0xffffffffu, m, off));
        float wv = exp2f((s - m) * LOG2E);
        float l = wv;
        #pragma unroll
        for (int off = 8; off > 0; off >>= 1)
            l += __shfl_xor_sync(0xffffffffu, l, off);
        if (lane < CT) w_sm[lane] = wv;
        if (lane == 0) { g_m[b*NC + c] = m; g_l[b*NC + c] = l; }
    }
    __syncthreads();

    // ---- Phase B: weighted accumulate from smem ----
    const float4* eS = (const float4*)es + wid*32 + lane;   // d4 = wid*32+lane
    float4 acc = make_float4(0.f, 0.f, 0.f, 0.f);
    #pragma unroll
    for (int t = 0; t < CT; t++) {
        float wv = w_sm[t];
        float4 v = eS[t*256];
        acc.x = fmaf(wv, v.x, acc.x); acc.y = fmaf(wv, v.y, acc.y);
        acc.z = fmaf(wv, v.z, acc.z); acc.w = fmaf(wv, v.w, acc.w);
    }
    ((float4*)(g_acc + (b*NC + c)*ENCD))[wid*32 + lane] = acc;
}

// ---------------------------------------------------------------------------
// Kernel B: combine chunk partials -> context. Grid (B), 256 threads.
// ---------------------------------------------------------------------------
__global__ void __launch_bounds__(256) attn_combine()
{
    const int b = blockIdx.x, tid = threadIdx.x;
    __shared__ float sm[NC], sl[NC], sf[NC];
    if (tid < NC) { sm[tid] = g_m[b*NC + tid]; sl[tid] = g_l[b*NC + tid]; }
    __syncthreads();
    float M = -INFINITY;
    #pragma unroll
    for (int c = 0; c < NC; c++) M = fmaxf(M, sm[c]);
    if (tid < NC) sf[tid] = exp2f((sm[tid] - M) * LOG2E);
    __syncthreads();
    float L = 0.0f;
    #pragma unroll
    for (int c = 0; c < NC; c++) L += sl[c] * sf[c];
    float invL = __fdividef(1.0f, L);

    const float4* ga = (const float4*)g_acc;
    float4 v = make_float4(0.f, 0.f, 0.f, 0.f);
    #pragma unroll 8
    for (int c = 0; c < NC; c++) {
        float4 a = ga[(b*NC + c)*256 + tid];
        float f = sf[c];
        v.x = fmaf(a.x, f, v.x); v.y = fmaf(a.y, f, v.y);
        v.z = fmaf(a.z, f, v.z); v.w = fmaf(a.w, f, v.w);
    }
    v.x *= invL; v.y *= invL; v.z *= invL; v.w *= invL;
    ((float4*)(g_ctx + b*ENCD))[tid] = v;
}

// ---------------------------------------------------------------------------
// Kernel C: z partials = x@Wk + h@Wr, packed f32x2 FMA.
// Grid (32 j-blocks, KSPLIT=19), 128 threads.
// ---------------------------------------------------------------------------
__global__ void __launch_bounds__(128) lstm_gemm(
    const float* __restrict__ pm, const float* __restrict__ h,
    const float* __restrict__ Wk, const float* __restrict__ Wr)
{
    const int tid = threadIdx.x;
    const int j   = blockIdx.x * 128 + tid;
    const int ks  = blockIdx.y;

    u64t acc2[16];
    #pragma unroll
    for (int i = 0; i < 16; i++) acc2[i] = 0ull;

    __shared__ __align__(16) float xs[TK * 34];   // xs[kk*34 + b]

    const int tile0 = ks * TPS;
    for (int tile = tile0; tile < tile0 + TPS; tile++) {
        const int kbase = tile * TK;
        __syncthreads();
        #pragma unroll
        for (int i = 0; i < 4; i++) {
            int idx = tid + 128*i;        // [0,512)
            int bb  = idx >> 4;
            int kk  = idx & 15;
            int k   = kbase + kk;
            float v;
            if (k < MELD)            v = pm[bb*MELD + k];
            else if (k < MELD+ENCD)  v = g_ctx[bb*ENCD + (k - MELD)];
            else                     v = h[bb*DECD + (k - MELD - ENCD)];
            xs[kk*34 + bb] = v;
        }
        __syncthreads();

        const float* wrow = (tile < 69)
            ? (Wk + (long)kbase*4096 + j)
            : (Wr + (long)(kbase - (MELD+ENCD))*4096 + j);

        #pragma unroll
        for (int kk = 0; kk < TK; kk++) {
            u64t w2 = pack2(wrow[kk*4096]);
            const u64t* xp = reinterpret_cast<const u64t*>(xs + kk*34);
            #pragma unroll
            for (int bb = 0; bb < 16; bb++)
                fma2(acc2[bb], xp[bb], w2);
        }
    }
    #pragma unroll
    for (int bb = 0; bb < 16; bb++) {
        float2 f = unpack2(acc2[bb]);
        g_zp[(ks*32 + 2*bb  )*4*DECD + j] = f.x;
        g_zp[(ks*32 + 2*bb+1)*4*DECD + j] = f.y;
    }
}

// ---------------------------------------------------------------------------
// Kernel D: sum K-split partials + bias, gates, write h_new/c_new.
// Grid 256 x 128 threads -> 32768 = B*DEC elements.
// ---------------------------------------------------------------------------
__global__ void __launch_bounds__(128) lstm_gates(
    const float* __restrict__ c_in, const float* __restrict__ bias,
    float* __restrict__ out)
{
    const int idx = blockIdx.x*128 + threadIdx.x;   // [0, 32768)
    const int b = idx >> 10, jj = idx & 1023;

    float zi = bias[jj], zf = bias[DECD + jj];
    float zg = bias[2*DECD + jj], zo = bias[3*DECD + jj];
    #pragma unroll
    for (int ks = 0; ks < KSPLIT; ks++) {
        const float* zp = g_zp + (ks*32 + b)*4*DECD;
        zi += zp[jj];
        zf += zp[DECD + jj];
        zg += zp[2*DECD + jj];
        zo += zp[3*DECD + jj];
    }
    float ig = fast_sig(zi), fg = fast_sig(zf), og = fast_sig(zo);
    float gg = fast_tanh(zg);
    float cn = fmaf(fg, c_in[idx], ig * gg);
    float hn = og * fast_tanh(cn);
    out[OFF_H + idx] = hn;
    out[OFF_C + idx] = cn;
}

// ---------------------------------------------------------------------------
// Kernel E: mel projection. Grid (B), block (96, 4): 4-way k-split + smem
// reduce. j in [0,80), slice ty covers k = ty*256 .. ty*256+255.
// ---------------------------------------------------------------------------
__global__ void __launch_bounds__(384) mel_proj(
    const float* __restrict__ pw, const float* __restrict__ pb,
    float* __restrict__ out)
{
    const int b = blockIdx.x;
    const int j = threadIdx.x;          // 0..95 (80 active)
    const int ty = threadIdx.y;         // 0..3
    __shared__ float red[4][96];

    float a0 = 0.f, a1 = 0.f, a2 = 0.f, a3 = 0.f;
    if (j < MELD) {
        const float* hn = out + OFF_H + b*DECD + ty*256;
        const float* pwk = pw + (long)(ty*256)*MELD + j;
        #pragma unroll 4
        for (int k = 0; k < 256; k += 4) {
            a0 = fmaf(hn[k  ], pwk[(k  )*MELD], a0);
            a1 = fmaf(hn[k+1], pwk[(k+1)*MELD], a1);
            a2 = fmaf(hn[k+2], pwk[(k+2)*MELD], a2);
            a3 = fmaf(hn[k+3], pwk[(k+3)*MELD], a3);
        }
    }
    red[ty][j] = (a0 + a1) + (a2 + a3);
    __syncthreads();
    if (ty == 0 && j < MELD) {
        out[OFF_MEL + b*MELD + j] =
            red[0][j] + red[1][j] + red[2][j] + red[3][j] + pb[j];
    }
}

// ---------------------------------------------------------------------------
extern "C" void kernel_launch(void* const* d_in, const int* in_sizes, int n_in,
                              void* d_out, int out_size)
{
    const float* pm    = (const float*)d_in[0];  // prev_mel_frame [32,80]
    const float* enc   = (const float*)d_in[1];  // encoder_outputs [32,1024,1024]
    const float* h     = (const float*)d_in[2];  // h [32,1024]
    const float* c     = (const float*)d_in[3];  // c [32,1024]
    const float* ascl  = (const float*)d_in[4];  // attn_scale [1024]
    const float* Wk    = (const float*)d_in[5];  // kernel [1104,4096]
    const float* Wr    = (const float*)d_in[6];  // rec_kernel [1024,4096]
    const float* bias  = (const float*)d_in[7];  // bias [4096]
    const float* pw    = (const float*)d_in[8];  // proj_w [1024,80]
    const float* pb    = (const float*)d_in[9];  // proj_b [80]
    float* out = (float*)d_out;

    // 64 KB dynamic smem opt-in (host attribute set; not a stream op).
    const int smemA = CT * ENCD * sizeof(float);
    cudaFuncSetAttribute(attn_partial,
                         cudaFuncAttributeMaxDynamicSharedMemorySize, smemA);

    dim3 gA(BB, NC);
    attn_partial<<<gA, 256, smemA>>>(enc, h, ascl);
    attn_combine<<<BB, 256>>>();
    dim3 gC(32, KSPLIT);
    lstm_gemm<<<gC, 128>>>(pm, h, Wk, Wr);
    lstm_gates<<<256, 128>>>(c, bias, out);
    dim3 bE(96, 4);
    mel_proj<<<BB, bE>>>(pw, pb, out);
}

// round 6
// speedup vs baseline: 1.0855x; 1.0855x over previous
#include <cuda_runtime.h>
#include <math.h>

// Problem dims
#define BB    32
#define TENC  1024
#define ENCD  1024
#define DECD  1024
#define MELD  80
// Attention split
#define NC    32          // chunks over T
#define CT    32          // timesteps per chunk
// LSTM GEMM
#define KTOT  2128        // 80 (mel) + 1024 (ctx) + 1024 (h)
#define TK    16
#define NTILES 133        // 2128/16
#define KSPLIT 19
#define TPS    7          // 133/19

// Output layout: [mel(32*80), h_new(32*1024), c_new(32*1024)]
#define OFF_MEL 0
#define OFF_H   (BB*MELD)
#define OFF_C   (BB*MELD + BB*DECD)

// Scratch (static device memory — no allocations allowed)
__device__ float g_m[BB*NC];
__device__ float g_l[BB*NC];
__device__ float g_acc[BB*NC*ENCD];
__device__ float g_ctx[BB*ENCD];
__device__ float g_zp[KSPLIT*BB*4*DECD];

#define LOG2E  1.4426950408889634f
#define LOG2E2 2.8853900817779268f

// HW tanh (MUFU.TANH) — attention scores only; error damped by softmax+GEMM.
__device__ __forceinline__ float tanhA(float x) {
    float y; asm("tanh.approx.f32 %0, %1;" : "=f"(y) : "f"(x)); return y;
}
// Accurate-ish versions for the LSTM gate outputs (written directly to d_out)
__device__ __forceinline__ float fast_tanh(float x) {
    float u = exp2f(x * LOG2E2);
    return 1.0f - __fdividef(2.0f, u + 1.0f);
}
__device__ __forceinline__ float fast_sig(float x) {
    return __fdividef(1.0f, 1.0f + exp2f(-LOG2E * x));
}

// f32x2 packed FMA helpers
typedef unsigned long long u64t;
__device__ __forceinline__ u64t pack2(float w) {
    u64t r; asm("mov.b64 %0, {%1, %1};" : "=l"(r) : "f"(w)); return r;
}
__device__ __forceinline__ void fma2(u64t& a, u64t x, u64t w) {
    asm("fma.rn.f32x2 %0, %1, %2, %0;" : "+l"(a) : "l"(x), "l"(w));
}
__device__ __forceinline__ float2 unpack2(u64t a) {
    float2 f; asm("mov.b64 {%0, %1}, %2;" : "=f"(f.x), "=f"(f.y) : "l"(a)); return f;
}

// ---------------------------------------------------------------------------
// Kernel A: attention chunk partials. Grid (B, NC), 256 threads (8 warps).
// h row kept in SMEM (not regs) -> ~60 regs/thread -> 4 CTAs/SM.
// Phase A: warp w computes scores of t = 4w..4w+3.
// Merge (1 warp): chunk-local softmax.
// Phase B: warp w owns D-slice [128w,128w+128), float4/lane over 32 t
//          (rows L1/L2-hot from phase A).
// ---------------------------------------------------------------------------
__global__ void __launch_bounds__(256) attn_partial(
    const float* __restrict__ enc, const float* __restrict__ h,
    const float* __restrict__ scale)
{
    const int b = blockIdx.x, c = blockIdx.y;
    const int tid = threadIdx.x;
    const int wid = tid >> 5, lane = tid & 31;

    __shared__ float4 hsm[256];          // full h row for this b (1024 floats)
    __shared__ float s_sm[CT];
    __shared__ float w_sm[CT];

    hsm[tid] = ((const float4*)(h + b*DECD))[tid];

    // scale slice in regs: quad d4 = lane + 32k, k=0..7
    float4 sc[8];
    const float4* s4 = (const float4*)scale;
    #pragma unroll
    for (int k = 0; k < 8; k++) sc[k] = s4[lane + 32*k];

    __syncthreads();

    const float* encb = enc + ((long)(b*TENC) + c*CT)*ENCD;

    // ---- Phase A ----
    #pragma unroll
    for (int i = 0; i < 4; i++) {
        const int t = wid*4 + i;
        const float4* eA = (const float4*)(encb + t*ENCD) + lane;
        float p0 = 0.f, p1 = 0.f, p2 = 0.f, p3 = 0.f;
        #pragma unroll
        for (int k = 0; k < 8; k++) {
            float4 e  = eA[32*k];
            float4 hv = hsm[lane + 32*k];
            p0 = fmaf(sc[k].x, tanhA(hv.x + e.x), p0);
            p1 = fmaf(sc[k].y, tanhA(hv.y + e.y), p1);
            p2 = fmaf(sc[k].z, tanhA(hv.z + e.z), p2);
            p3 = fmaf(sc[k].w, tanhA(hv.w + e.w), p3);
        }
        float s = (p0 + p1) + (p2 + p3);
        #pragma unroll
        for (int off = 16; off > 0; off >>= 1)
            s += __shfl_xor_sync(0xffffffffu, s, off);
        if (lane == 0) s_sm[t] = s;
    }
    __syncthreads();

    // ---- Merge: chunk-local softmax (warp 0) ----
    if (wid == 0) {
        float s = s_sm[lane];
        float m = s;
        #pragma unroll
        for (int off = 16; off > 0; off >>= 1)
            m = fmaxf(m, __shfl_xor_sync(0xffffffffu, m, off));
        float wv = exp2f((s - m) * LOG2E);
        float l = wv;
        #pragma unroll
        for (int off = 16; off > 0; off >>= 1)
            l += __shfl_xor_sync(0xffffffffu, l, off);
        w_sm[lane] = wv;
        if (lane == 0) { g_m[b*NC + c] = m; g_l[b*NC + c] = l; }
    }
    __syncthreads();

    // ---- Phase B: weighted accumulate (rows cache-hot) ----
    const float4* eB = (const float4*)encb + wid*32 + lane;
    float4 acc = make_float4(0.f, 0.f, 0.f, 0.f);
    #pragma unroll 8
    for (int t = 0; t < CT; t++) {
        float wv = w_sm[t];
        float4 v = eB[t*256];
        acc.x = fmaf(wv, v.x, acc.x); acc.y = fmaf(wv, v.y, acc.y);
        acc.z = fmaf(wv, v.z, acc.z); acc.w = fmaf(wv, v.w, acc.w);
    }
    ((float4*)(g_acc + (b*NC + c)*ENCD))[wid*32 + lane] = acc;
}

// ---------------------------------------------------------------------------
// Kernel B: combine chunk partials -> context. Grid (B), 256 threads.
// ---------------------------------------------------------------------------
__global__ void __launch_bounds__(256) attn_combine()
{
    const int b = blockIdx.x, tid = threadIdx.x;
    __shared__ float sm[NC], sl[NC], sf[NC];
    if (tid < NC) { sm[tid] = g_m[b*NC + tid]; sl[tid] = g_l[b*NC + tid]; }
    __syncthreads();
    float M = -INFINITY;
    #pragma unroll
    for (int c = 0; c < NC; c++) M = fmaxf(M, sm[c]);
    if (tid < NC) sf[tid] = exp2f((sm[tid] - M) * LOG2E);
    __syncthreads();
    float L = 0.0f;
    #pragma unroll
    for (int c = 0; c < NC; c++) L += sl[c] * sf[c];
    float invL = __fdividef(1.0f, L);

    const float4* ga = (const float4*)g_acc;
    float4 v = make_float4(0.f, 0.f, 0.f, 0.f);
    #pragma unroll 8
    for (int c = 0; c < NC; c++) {
        float4 a = ga[(b*NC + c)*256 + tid];
        float f = sf[c];
        v.x = fmaf(a.x, f, v.x); v.y = fmaf(a.y, f, v.y);
        v.z = fmaf(a.z, f, v.z); v.w = fmaf(a.w, f, v.w);
    }
    v.x *= invL; v.y *= invL; v.z *= invL; v.w *= invL;
    ((float4*)(g_ctx + b*ENCD))[tid] = v;
}

// ---------------------------------------------------------------------------
// Kernel C: z partials = x@Wk + h@Wr, packed f32x2 FMA.
// Grid (32 j-blocks, KSPLIT=19), 128 threads.
// ---------------------------------------------------------------------------
__global__ void __launch_bounds__(128) lstm_gemm(
    const float* __restrict__ pm, const float* __restrict__ h,
    const float* __restrict__ Wk, const float* __restrict__ Wr)
{
    const int tid = threadIdx.x;
    const int j   = blockIdx.x * 128 + tid;
    const int ks  = blockIdx.y;

    u64t acc2[16];
    #pragma unroll
    for (int i = 0; i < 16; i++) acc2[i] = 0ull;

    __shared__ __align__(16) float xs[TK * 34];   // xs[kk*34 + b]

    const int tile0 = ks * TPS;
    for (int tile = tile0; tile < tile0 + TPS; tile++) {
        const int kbase = tile * TK;
        __syncthreads();
        #pragma unroll
        for (int i = 0; i < 4; i++) {
            int idx = tid + 128*i;        // [0,512)
            int bb  = idx >> 4;
            int kk  = idx & 15;
            int k   = kbase + kk;
            float v;
            if (k < MELD)            v = pm[bb*MELD + k];
            else if (k < MELD+ENCD)  v = g_ctx[bb*ENCD + (k - MELD)];
            else                     v = h[bb*DECD + (k - MELD - ENCD)];
            xs[kk*34 + bb] = v;
        }
        __syncthreads();

        const float* wrow = (tile < 69)
            ? (Wk + (long)kbase*4096 + j)
            : (Wr + (long)(kbase - (MELD+ENCD))*4096 + j);

        #pragma unroll
        for (int kk = 0; kk < TK; kk++) {
            u64t w2 = pack2(wrow[kk*4096]);
            const u64t* xp = reinterpret_cast<const u64t*>(xs + kk*34);
            #pragma unroll
            for (int bb = 0; bb < 16; bb++)
                fma2(acc2[bb], xp[bb], w2);
        }
    }
    #pragma unroll
    for (int bb = 0; bb < 16; bb++) {
        float2 f = unpack2(acc2[bb]);
        g_zp[(ks*32 + 2*bb  )*4*DECD + j] = f.x;
        g_zp[(ks*32 + 2*bb+1)*4*DECD + j] = f.y;
    }
}

// ---------------------------------------------------------------------------
// Kernel D: sum K-split partials + bias, gates, write h_new/c_new.
// Grid 128 x 256 threads -> 32768 = B*DEC elements. (R2-measured shape.)
// ---------------------------------------------------------------------------
__global__ void __launch_bounds__(256) lstm_gates(
    const float* __restrict__ c_in, const float* __restrict__ bias,
    float* __restrict__ out)
{
    const int idx = blockIdx.x*256 + threadIdx.x;   // [0, 32768)
    const int b = idx >> 10, jj = idx & 1023;

    float zi = bias[jj], zf = bias[DECD + jj];
    float zg = bias[2*DECD + jj], zo = bias[3*DECD + jj];
    #pragma unroll
    for (int ks = 0; ks < KSPLIT; ks++) {
        const float* zp = g_zp + (ks*32 + b)*4*DECD;
        zi += zp[jj];
        zf += zp[DECD + jj];
        zg += zp[2*DECD + jj];
        zo += zp[3*DECD + jj];
    }
    float ig = fast_sig(zi), fg = fast_sig(zf), og = fast_sig(zo);
    float gg = fast_tanh(zg);
    float cn = fmaf(fg, c_in[idx], ig * gg);
    float hn = og * fast_tanh(cn);
    out[OFF_H + idx] = hn;
    out[OFF_C + idx] = cn;
}

// ---------------------------------------------------------------------------
// Kernel E: mel projection. Grid (B), block (96, 4): 4-way k-split + smem
// reduce. j in [0,80), slice ty covers k = ty*256 .. ty*256+255.
// ---------------------------------------------------------------------------
__global__ void __launch_bounds__(384) mel_proj(
    const float* __restrict__ pw, const float* __restrict__ pb,
    float* __restrict__ out)
{
    const int b = blockIdx.x;
    const int j = threadIdx.x;          // 0..95 (80 active)
    const int ty = threadIdx.y;         // 0..3
    __shared__ float red[4][96];

    float a0 = 0.f, a1 = 0.f, a2 = 0.f, a3 = 0.f;
    if (j < MELD) {
        const float* hn = out + OFF_H + b*DECD + ty*256;
        const float* pwk = pw + (long)(ty*256)*MELD + j;
        #pragma unroll 4
        for (int k = 0; k < 256; k += 4) {
            a0 = fmaf(hn[k  ], pwk[(k  )*MELD], a0);
            a1 = fmaf(hn[k+1], pwk[(k+1)*MELD], a1);
            a2 = fmaf(hn[k+2], pwk[(k+2)*MELD], a2);
            a3 = fmaf(hn[k+3], pwk[(k+3)*MELD], a3);
        }
    }
    red[ty][j] = (a0 + a1) + (a2 + a3);
    __syncthreads();
    if (ty == 0 && j < MELD) {
        out[OFF_MEL + b*MELD + j] =
            red[0][j] + red[1][j] + red[2][j] + red[3][j] + pb[j];
    }
}

// ---------------------------------------------------------------------------
extern "C" void kernel_launch(void* const* d_in, const int* in_sizes, int n_in,
                              void* d_out, int out_size)
{
    const float* pm    = (const float*)d_in[0];  // prev_mel_frame [32,80]
    const float* enc   = (const float*)d_in[1];  // encoder_outputs [32,1024,1024]
    const float* h     = (const float*)d_in[2];  // h [32,1024]
    const float* c     = (const float*)d_in[3];  // c [32,1024]
    const float* ascl  = (const float*)d_in[4];  // attn_scale [1024]
    const float* Wk    = (const float*)d_in[5];  // kernel [1104,4096]
    const float* Wr    = (const float*)d_in[6];  // rec_kernel [1024,4096]
    const float* bias  = (const float*)d_in[7];  // bias [4096]
    const float* pw    = (const float*)d_in[8];  // proj_w [1024,80]
    const float* pb    = (const float*)d_in[9];  // proj_b [80]
    float* out = (float*)d_out;

    dim3 gA(BB, NC);
    attn_partial<<<gA, 256>>>(enc, h, ascl);
    attn_combine<<<BB, 256>>>();
    dim3 gC(32, KSPLIT);
    lstm_gemm<<<gC, 128>>>(pm, h, Wk, Wr);
    lstm_gates<<<128, 256>>>(c, bias, out);
    dim3 bE(96, 4);
    mel_proj<<<BB, bE>>>(pw, pb, out);
}